// round 3
// baseline (speedup 1.0000x reference)
#include <cuda_runtime.h>
#include <cstdint>
#include <cmath>

// Problem dims (fixed)
#define B_DIM 8
#define L_DIM 4096
#define D_DIM 512
#define M_DIM (B_DIM * L_DIM)   // 32768
#define N1 (2 * D_DIM)          // 1024
#define K1 (D_DIM)              // 512
#define N2 (D_DIM)              // 512
#define K2 (2 * D_DIM)          // 1024

#define CHUNK 256
#define NCHUNK (L_DIM / CHUNK)  // 16

// Scratch (device globals; allocation is banned)
__device__ float g_u[(size_t)M_DIM * N1];                    // 128 MB intermediate
__device__ float g_wo2[(size_t)N2 * K2];                     // permuted Wo
__device__ float g_carry[(size_t)B_DIM * NCHUNK * D_DIM * 2];// chunk carries (complex)

// ---------------------------------------------------------------------------
// tf32 TN GEMM: C[M,N] = A[M,K] * W[N,K]^T + bias, optional ReLU.
// Block tile 128x128, BK=16, 256 threads (8 warps, each 64x32), cp.async 2-stage.
// ---------------------------------------------------------------------------
#define BM 128
#define BN 128
#define BK 16
#define SST 20  // shared row stride (floats): pad 16->20, conflict-free frag loads

__device__ __forceinline__ uint32_t f2tf32(float f) {
    uint32_t u;
    asm("cvt.rna.tf32.f32 %0, %1;" : "=r"(u) : "f"(f));
    return u;
}

__device__ __forceinline__ void mma_tf32(float* c, const uint32_t* a, const uint32_t* b) {
    asm volatile(
        "mma.sync.aligned.m16n8k8.row.col.f32.tf32.tf32.f32 "
        "{%0,%1,%2,%3},{%4,%5,%6,%7},{%8,%9},{%0,%1,%2,%3};\n"
        : "+f"(c[0]), "+f"(c[1]), "+f"(c[2]), "+f"(c[3])
        : "r"(a[0]), "r"(a[1]), "r"(a[2]), "r"(a[3]), "r"(b[0]), "r"(b[1]));
}

template <bool RELU>
__global__ void __launch_bounds__(256)
gemm_tn(const float* __restrict__ A, const float* __restrict__ W,
        const float* __restrict__ bias, float* __restrict__ C,
        int M, int N, int K)
{
    __shared__ float As[2][BM * SST];
    __shared__ float Bs[2][BN * SST];

    const int tid  = threadIdx.x;
    const int warp = tid >> 5;
    const int lane = tid & 31;
    const int g    = lane >> 2;   // group id (row within fragment)
    const int tig  = lane & 3;    // thread-in-group (col within fragment)
    const int wm   = warp & 1;    // warp row: 0..1 (64 rows each)
    const int wn   = warp >> 1;   // warp col: 0..3 (32 cols each)

    const int bm0 = blockIdx.y * BM;
    const int bn0 = blockIdx.x * BN;

    // global->shared load mapping: 256 threads, each 2x 16B per matrix tile
    const int lrow = tid >> 2;          // 0..63
    const int lk4  = (tid & 3) * 4;     // 0,4,8,12

    const float* gA = A + (size_t)(bm0 + lrow) * K + lk4;
    const float* gB = W + (size_t)(bn0 + lrow) * K + lk4;

    const uint32_t sA0 = (uint32_t)__cvta_generic_to_shared(&As[0][0]);
    const uint32_t sB0 = (uint32_t)__cvta_generic_to_shared(&Bs[0][0]);
    const uint32_t soff = (uint32_t)(lrow * SST + lk4) * 4u;
    const uint32_t halfoff = 64u * SST * 4u;
    const uint32_t bufstride = (uint32_t)(BM * SST) * 4u;

    float acc[4][4][4];
#pragma unroll
    for (int mt = 0; mt < 4; mt++)
#pragma unroll
        for (int nt = 0; nt < 4; nt++)
#pragma unroll
            for (int i = 0; i < 4; i++) acc[mt][nt][i] = 0.f;

    const int KT = K / BK;

    // prologue: tile 0 -> buf 0
    {
        const float* a = gA;
        const float* b = gB;
        uint32_t sa = sA0 + soff;
        uint32_t sb = sB0 + soff;
        asm volatile("cp.async.ca.shared.global [%0], [%1], 16;\n" ::"r"(sa), "l"(a));
        asm volatile("cp.async.ca.shared.global [%0], [%1], 16;\n" ::"r"(sa + halfoff), "l"(a + (size_t)64 * K));
        asm volatile("cp.async.ca.shared.global [%0], [%1], 16;\n" ::"r"(sb), "l"(b));
        asm volatile("cp.async.ca.shared.global [%0], [%1], 16;\n" ::"r"(sb + halfoff), "l"(b + (size_t)64 * K));
        asm volatile("cp.async.commit_group;\n");
    }

    for (int kt = 0; kt < KT; kt++) {
        const int buf = kt & 1;
        if (kt + 1 < KT) {
            const float* a = gA + (size_t)(kt + 1) * BK;
            const float* b = gB + (size_t)(kt + 1) * BK;
            uint32_t sa = sA0 + (uint32_t)(buf ^ 1) * bufstride + soff;
            uint32_t sb = sB0 + (uint32_t)(buf ^ 1) * bufstride + soff;
            asm volatile("cp.async.ca.shared.global [%0], [%1], 16;\n" ::"r"(sa), "l"(a));
            asm volatile("cp.async.ca.shared.global [%0], [%1], 16;\n" ::"r"(sa + halfoff), "l"(a + (size_t)64 * K));
            asm volatile("cp.async.ca.shared.global [%0], [%1], 16;\n" ::"r"(sb), "l"(b));
            asm volatile("cp.async.ca.shared.global [%0], [%1], 16;\n" ::"r"(sb + halfoff), "l"(b + (size_t)64 * K));
            asm volatile("cp.async.commit_group;\n");
            asm volatile("cp.async.wait_group 1;\n");
        } else {
            asm volatile("cp.async.wait_group 0;\n");
        }
        __syncthreads();

        const float* as = &As[buf][0];
        const float* bs = &Bs[buf][0];

#pragma unroll
        for (int ks = 0; ks < 2; ks++) {
            const int k0 = ks * 8;
            uint32_t af[4][4], bf[4][2];
#pragma unroll
            for (int mt = 0; mt < 4; mt++) {
                const int r = wm * 64 + mt * 16;
                af[mt][0] = f2tf32(as[(r + g) * SST + k0 + tig]);
                af[mt][1] = f2tf32(as[(r + g + 8) * SST + k0 + tig]);
                af[mt][2] = f2tf32(as[(r + g) * SST + k0 + tig + 4]);
                af[mt][3] = f2tf32(as[(r + g + 8) * SST + k0 + tig + 4]);
            }
#pragma unroll
            for (int nt = 0; nt < 4; nt++) {
                const int cc = wn * 32 + nt * 8;
                bf[nt][0] = f2tf32(bs[(cc + g) * SST + k0 + tig]);
                bf[nt][1] = f2tf32(bs[(cc + g) * SST + k0 + tig + 4]);
            }
#pragma unroll
            for (int mt = 0; mt < 4; mt++)
#pragma unroll
                for (int nt = 0; nt < 4; nt++)
                    mma_tf32(acc[mt][nt], af[mt], bf[nt]);
        }
        __syncthreads();
    }

    // epilogue: bias (+ ReLU), float2 stores
#pragma unroll
    for (int mt = 0; mt < 4; mt++) {
#pragma unroll
        for (int nt = 0; nt < 4; nt++) {
            const int row = bm0 + wm * 64 + mt * 16 + g;
            const int col = bn0 + wn * 32 + nt * 8 + tig * 2;
            const float b0 = bias[col];
            const float b1 = bias[col + 1];
            float2 v0, v1;
            v0.x = acc[mt][nt][0] + b0; v0.y = acc[mt][nt][1] + b1;
            v1.x = acc[mt][nt][2] + b0; v1.y = acc[mt][nt][3] + b1;
            if (RELU) {
                v0.x = fmaxf(v0.x, 0.f); v0.y = fmaxf(v0.y, 0.f);
                v1.x = fmaxf(v1.x, 0.f); v1.y = fmaxf(v1.y, 0.f);
            }
            *(float2*)&C[(size_t)row * N + col] = v0;
            *(float2*)&C[(size_t)(row + 8) * N + col] = v1;
        }
    }
}

// ---------------------------------------------------------------------------
// Scan kernels: h_t = lambda_d * h_{t-1} + x_t (complex), chunked 3-pass.
// u layout: [B, L, D] of float2 (real=u[...,2d], imag=u[...,2d+1]), in-place.
// ---------------------------------------------------------------------------
__device__ __forceinline__ float2 cmul(float2 a, float2 b) {
    return make_float2(a.x * b.x - a.y * b.y, a.x * b.y + a.y * b.x);
}

__global__ void __launch_bounds__(256)
scan_local(float* __restrict__ u, const float* __restrict__ pl,
           float* __restrict__ carry)
{
    const int idx = blockIdx.x * blockDim.x + threadIdx.x;  // B*NCHUNK*D
    const int d = idx % D_DIM;
    const int c = (idx / D_DIM) % NCHUNK;
    const int b = idx / (D_DIM * NCHUNK);

    const float v  = expf(pl[d]);
    const float th = expf(pl[D_DIM + d]);
    const float mg = expf(-v);
    const float2 lam = make_float2(mg * cosf(th), mg * sinf(th));

    float2* u2 = (float2*)u;
    size_t off = (size_t)(b * L_DIM + c * CHUNK) * D_DIM + d;

    float2 h = make_float2(0.f, 0.f);
#pragma unroll 4
    for (int t = 0; t < CHUNK; t++) {
        float2 x = u2[off];
        float2 nh;
        nh.x = fmaf(lam.x, h.x, fmaf(-lam.y, h.y, x.x));
        nh.y = fmaf(lam.x, h.y, fmaf(lam.y, h.x, x.y));
        h = nh;
        u2[off] = h;
        off += D_DIM;
    }
    ((float2*)carry)[(size_t)(b * NCHUNK + c) * D_DIM + d] = h;
}

__global__ void __launch_bounds__(256)
scan_combine(float* __restrict__ carry, const float* __restrict__ pl)
{
    const int idx = blockIdx.x * blockDim.x + threadIdx.x;  // B*D
    const int d = idx % D_DIM;
    const int b = idx / D_DIM;

    const float v  = expf(pl[d]);
    const float th = expf(pl[D_DIM + d]);
    // lambda^CHUNK via double trig (large angle: avoid fast-math range issues)
    const double ang = (double)th * (double)CHUNK;
    const float mg = expf(-v * (float)CHUNK);
    const float2 lamT = make_float2(mg * (float)cos(ang), mg * (float)sin(ang));

    float2* c2 = (float2*)carry;
    float2 E = make_float2(0.f, 0.f);
#pragma unroll
    for (int c = 0; c < NCHUNK; c++) {
        const size_t i = (size_t)(b * NCHUNK + c) * D_DIM + d;
        float2 loc = c2[i];
        c2[i] = E;  // store exclusive combined carry
        float2 nE;
        nE.x = fmaf(lamT.x, E.x, fmaf(-lamT.y, E.y, loc.x));
        nE.y = fmaf(lamT.x, E.y, fmaf(lamT.y, E.x, loc.y));
        E = nE;
    }
}

__global__ void __launch_bounds__(256)
scan_fix(float* __restrict__ u, const float* __restrict__ pl,
         const float* __restrict__ carry)
{
    const int idx = blockIdx.x * blockDim.x + threadIdx.x;  // B*NCHUNK*D
    const int d = idx % D_DIM;
    const int c = (idx / D_DIM) % NCHUNK;
    const int b = idx / (D_DIM * NCHUNK);

    const float v  = expf(pl[d]);
    const float th = expf(pl[D_DIM + d]);
    const float gamma = expf(pl[2 * D_DIM + d]);
    const float mg = expf(-v);
    const float2 lam = make_float2(mg * cosf(th), mg * sinf(th));

    const float2 E = ((const float2*)carry)[(size_t)(b * NCHUNK + c) * D_DIM + d];

    float2* u2 = (float2*)u;
    size_t off = (size_t)(b * L_DIM + c * CHUNK) * D_DIM + d;

    float2 f = lam;  // lambda^(t+1), iterated
#pragma unroll 4
    for (int t = 0; t < CHUNK; t++) {
        float2 h = u2[off];
        h.x = (h.x + f.x * E.x - f.y * E.y) * gamma;
        h.y = (h.y + f.x * E.y + f.y * E.x) * gamma;
        u2[off] = h;
        float2 nf;
        nf.x = f.x * lam.x - f.y * lam.y;
        nf.y = f.x * lam.y + f.y * lam.x;
        f = nf;
        off += D_DIM;
    }
}

// Wo [N2, 2D] -> Wo2 interleaved so GEMM2 consumes (Re,Im)-interleaved h:
// Wo2[n, 2d] = Wo[n, d]; Wo2[n, 2d+1] = Wo[n, D+d]
__global__ void __launch_bounds__(256)
permute_wo(const float* __restrict__ Wo, float* __restrict__ Wo2)
{
    const int idx = blockIdx.x * blockDim.x + threadIdx.x;  // N2*D
    const int d = idx % D_DIM;
    const int n = idx / D_DIM;
    Wo2[(size_t)n * K2 + 2 * d]     = Wo[(size_t)n * K2 + d];
    Wo2[(size_t)n * K2 + 2 * d + 1] = Wo[(size_t)n * K2 + D_DIM + d];
}

// ---------------------------------------------------------------------------
extern "C" void kernel_launch(void* const* d_in, const int* in_sizes, int n_in,
                              void* d_out, int out_size)
{
    (void)in_sizes; (void)n_in; (void)out_size;
    const float* inputs = (const float*)d_in[0];
    const float* Wi     = (const float*)d_in[1];
    const float* bi     = (const float*)d_in[2];
    const float* Wo     = (const float*)d_in[3];
    const float* bo     = (const float*)d_in[4];
    const float* pl     = (const float*)d_in[5];
    float* out = (float*)d_out;

    float *u, *wo2, *carry;
    cudaGetSymbolAddress((void**)&u, g_u);
    cudaGetSymbolAddress((void**)&wo2, g_wo2);
    cudaGetSymbolAddress((void**)&carry, g_carry);

    // Wo permute (cheap; run every call for determinism)
    permute_wo<<<(N2 * D_DIM) / 256, 256>>>(Wo, wo2);

    // GEMM1: u = inputs @ Wi^T + bi
    {
        dim3 grid(N1 / BN, M_DIM / BM);
        gemm_tn<false><<<grid, 256>>>(inputs, Wi, bi, u, M_DIM, N1, K1);
    }

    // chunked complex scan (in-place over u) + gamma
    scan_local<<<(B_DIM * NCHUNK * D_DIM) / 256, 256>>>(u, pl, carry);
    scan_combine<<<(B_DIM * D_DIM) / 256, 256>>>(carry, pl);
    scan_fix<<<(B_DIM * NCHUNK * D_DIM) / 256, 256>>>(u, pl, carry);

    // GEMM2: out = relu(h_interleaved @ Wo2^T + bo)
    {
        dim3 grid(N2 / BN, M_DIM / BM);
        gemm_tn<true><<<grid, 256>>>(u, wo2, bo, out, M_DIM, N2, K2);
    }
}

// round 6
// speedup vs baseline: 1.5002x; 1.5002x over previous
#include <cuda_runtime.h>
#include <cuda_fp16.h>
#include <cstdint>
#include <cmath>

// ---------------------------------------------------------------------------
// Problem dims (fixed)
#define B_DIM 8
#define L_DIM 4096
#define D_DIM 512
#define M_DIM (B_DIM * L_DIM)   // 32768
#define N1 (2 * D_DIM)          // 1024
#define K1 (D_DIM)              // 512
#define N2 (D_DIM)              // 512
#define K2 (2 * D_DIM)          // 1024

#define CHUNK 256
#define NCHUNK (L_DIM / CHUNK)  // 16

// Scratch (device globals; allocation is banned)
__device__ __align__(1024) float  g_u[(size_t)M_DIM * N1];      // 128 MB fp32 (GEMM1 out / scan)
__device__ __align__(1024) __half g_inh[(size_t)M_DIM * K1];    // 32 MB  half inputs
__device__ __align__(1024) __half g_uh[(size_t)M_DIM * K2];     // 64 MB  half scan output (GEMM2 A)
__device__ __align__(1024) __half g_wih[(size_t)N1 * K1];       // 1 MB   half Wi
__device__ __align__(1024) __half g_wo2h[(size_t)N2 * K2];      // 1 MB   half permuted Wo
__device__ __align__(1024) float  g_carry[(size_t)B_DIM * NCHUNK * D_DIM * 2];

// ---------------------------------------------------------------------------
// fp16 TN GEMM: C[M,N] = A[M,K] * W[N,K]^T + bias (optional ReLU), fp32 accum.
// Block tile 128x128, BK=32 halves, 256 threads (8 warps, each 64x32),
// 3-stage cp.async pipeline, padded smem (SSTH=40 halves, conflict-free).
// ---------------------------------------------------------------------------
#define BMh 128
#define BNh 128
#define BKh 32
#define SSTH 40                     // halves per smem row (32 + 8 pad)
#define STAGE_HALVES (BMh * SSTH)   // per matrix per stage = 5120 halves
#define GEMM_SMEM (2 * 3 * STAGE_HALVES * 2)  // A+B, 3 stages, bytes = 61440

__device__ __forceinline__ void mma_f16(float* c, const uint32_t* a, const uint32_t* b) {
    asm volatile(
        "mma.sync.aligned.m16n8k16.row.col.f32.f16.f16.f32 "
        "{%0,%1,%2,%3},{%4,%5,%6,%7},{%8,%9},{%0,%1,%2,%3};\n"
        : "+f"(c[0]), "+f"(c[1]), "+f"(c[2]), "+f"(c[3])
        : "r"(a[0]), "r"(a[1]), "r"(a[2]), "r"(a[3]), "r"(b[0]), "r"(b[1]));
}

// issue one stage of cp.async loads: A[128 x 32h] + B[128 x 32h]
__device__ __forceinline__ void ld_stage(uint32_t sA, uint32_t sB,
                                         const __half* gA, const __half* gB,
                                         int K, int row, int ch)
{
    const uint32_t so = (uint32_t)(row * SSTH + ch * 8) * 2u;
    const uint32_t so2 = so + (uint32_t)(64 * SSTH) * 2u;
    const __half* a0 = gA + (size_t)row * K + ch * 8;
    const __half* b0 = gB + (size_t)row * K + ch * 8;
    asm volatile("cp.async.ca.shared.global [%0], [%1], 16;\n" ::"r"(sA + so), "l"(a0));
    asm volatile("cp.async.ca.shared.global [%0], [%1], 16;\n" ::"r"(sA + so2), "l"(a0 + (size_t)64 * K));
    asm volatile("cp.async.ca.shared.global [%0], [%1], 16;\n" ::"r"(sB + so), "l"(b0));
    asm volatile("cp.async.ca.shared.global [%0], [%1], 16;\n" ::"r"(sB + so2), "l"(b0 + (size_t)64 * K));
    asm volatile("cp.async.commit_group;\n");
}

template <bool RELU>
__global__ void __launch_bounds__(256, 2)
gemm_h(const __half* __restrict__ A, const __half* __restrict__ W,
       const float* __restrict__ bias, float* __restrict__ C,
       int N, int K)
{
    extern __shared__ __align__(16) __half smem[];
    __half* As = smem;                       // [3][128*SSTH]
    __half* Bs = smem + 3 * STAGE_HALVES;    // [3][128*SSTH]

    const int tid  = threadIdx.x;
    const int warp = tid >> 5;
    const int lane = tid & 31;
    const int g    = lane >> 2;   // 0..7
    const int tig  = lane & 3;    // 0..3
    const int wm   = warp & 1;    // 0..1 (64 rows each)
    const int wn   = warp >> 1;   // 0..3 (32 cols each)

    const int bm0 = blockIdx.y * BMh;
    const int bn0 = blockIdx.x * BNh;

    const int lrow = tid >> 2;    // 0..63
    const int lch  = tid & 3;     // 0..3

    const __half* gA = A + (size_t)bm0 * K;
    const __half* gB = W + (size_t)bn0 * K;

    const uint32_t sA0 = (uint32_t)__cvta_generic_to_shared(As);
    const uint32_t sB0 = (uint32_t)__cvta_generic_to_shared(Bs);
    const uint32_t bufB = (uint32_t)STAGE_HALVES * 2u;  // bytes per stage

    float acc[4][4][4];
#pragma unroll
    for (int mt = 0; mt < 4; mt++)
#pragma unroll
        for (int nt = 0; nt < 4; nt++)
#pragma unroll
            for (int i = 0; i < 4; i++) acc[mt][nt][i] = 0.f;

    const int KT = K / BKh;

    // prologue: stages 0 and 1
    ld_stage(sA0, sB0, gA, gB, K, lrow, lch);
    ld_stage(sA0 + bufB, sB0 + bufB, gA + BKh, gB + BKh, K, lrow, lch);

    for (int kt = 0; kt < KT; kt++) {
        // wait for group kt (allow 1 newer pending unless it doesn't exist)
        if (kt + 1 < KT) asm volatile("cp.async.wait_group 1;\n");
        else             asm volatile("cp.async.wait_group 0;\n");
        __syncthreads();

        // prefetch tile kt+2 into buf (kt+2)%3 (safe: that buf's readers done)
        if (kt + 2 < KT) {
            const uint32_t bo = (uint32_t)((kt + 2) % 3) * bufB;
            ld_stage(sA0 + bo, sB0 + bo, gA + (size_t)(kt + 2) * BKh,
                     gB + (size_t)(kt + 2) * BKh, K, lrow, lch);
        }

        const __half* as = As + (kt % 3) * STAGE_HALVES;
        const __half* bs = Bs + (kt % 3) * STAGE_HALVES;

#pragma unroll
        for (int ks = 0; ks < 2; ks++) {
            const int k0 = ks * 16;
            uint32_t af[4][4], bf[4][2];
#pragma unroll
            for (int mt = 0; mt < 4; mt++) {
                const int r = wm * 64 + mt * 16;
                af[mt][0] = *(const uint32_t*)&as[(r + g) * SSTH + k0 + tig * 2];
                af[mt][1] = *(const uint32_t*)&as[(r + g + 8) * SSTH + k0 + tig * 2];
                af[mt][2] = *(const uint32_t*)&as[(r + g) * SSTH + k0 + 8 + tig * 2];
                af[mt][3] = *(const uint32_t*)&as[(r + g + 8) * SSTH + k0 + 8 + tig * 2];
            }
#pragma unroll
            for (int nt = 0; nt < 4; nt++) {
                const int cc = wn * 32 + nt * 8;
                bf[nt][0] = *(const uint32_t*)&bs[(cc + g) * SSTH + k0 + tig * 2];
                bf[nt][1] = *(const uint32_t*)&bs[(cc + g) * SSTH + k0 + 8 + tig * 2];
            }
#pragma unroll
            for (int mt = 0; mt < 4; mt++)
#pragma unroll
                for (int nt = 0; nt < 4; nt++)
                    mma_f16(acc[mt][nt], af[mt], bf[nt]);
        }
        __syncthreads();
    }

    // epilogue: bias (+ ReLU), float2 stores
#pragma unroll
    for (int mt = 0; mt < 4; mt++) {
#pragma unroll
        for (int nt = 0; nt < 4; nt++) {
            const int row = bm0 + wm * 64 + mt * 16 + g;
            const int col = bn0 + wn * 32 + nt * 8 + tig * 2;
            const float b0 = bias[col];
            const float b1 = bias[col + 1];
            float2 v0, v1;
            v0.x = acc[mt][nt][0] + b0; v0.y = acc[mt][nt][1] + b1;
            v1.x = acc[mt][nt][2] + b0; v1.y = acc[mt][nt][3] + b1;
            if (RELU) {
                v0.x = fmaxf(v0.x, 0.f); v0.y = fmaxf(v0.y, 0.f);
                v1.x = fmaxf(v1.x, 0.f); v1.y = fmaxf(v1.y, 0.f);
            }
            *(float2*)&C[(size_t)row * N + col] = v0;
            *(float2*)&C[(size_t)(row + 8) * N + col] = v1;
        }
    }
}

// ---------------------------------------------------------------------------
// Scan kernels: h_t = lambda_d * h_{t-1} + x_t (complex), chunked 2-pass.
// u layout: [B, L, D] of float2 (re, im) interleaved.
// ---------------------------------------------------------------------------
__global__ void __launch_bounds__(256)
scan_local(float* __restrict__ u, const float* __restrict__ pl,
           float* __restrict__ carry)
{
    const int idx = blockIdx.x * blockDim.x + threadIdx.x;  // B*NCHUNK*D
    const int d = idx % D_DIM;
    const int c = (idx / D_DIM) % NCHUNK;
    const int b = idx / (D_DIM * NCHUNK);

    const float v  = expf(pl[d]);
    const float th = expf(pl[D_DIM + d]);
    const float mg = expf(-v);
    const float2 lam = make_float2(mg * cosf(th), mg * sinf(th));

    float2* u2 = (float2*)u;
    size_t off = (size_t)(b * L_DIM + c * CHUNK) * D_DIM + d;

    float2 h = make_float2(0.f, 0.f);
#pragma unroll 4
    for (int t = 0; t < CHUNK; t++) {
        float2 x = u2[off];
        float2 nh;
        nh.x = fmaf(lam.x, h.x, fmaf(-lam.y, h.y, x.x));
        nh.y = fmaf(lam.x, h.y, fmaf(lam.y, h.x, x.y));
        h = nh;
        u2[off] = h;
        off += D_DIM;
    }
    ((float2*)carry)[(size_t)(b * NCHUNK + c) * D_DIM + d] = h;
}

// Fused combine + fixup + gamma; writes half output for GEMM2 directly.
__global__ void __launch_bounds__(256)
scan_fix(const float* __restrict__ u, const float* __restrict__ pl,
         const float* __restrict__ carry, __half* __restrict__ uh)
{
    const int idx = blockIdx.x * blockDim.x + threadIdx.x;  // B*NCHUNK*D
    const int d = idx % D_DIM;
    const int c = (idx / D_DIM) % NCHUNK;
    const int b = idx / (D_DIM * NCHUNK);

    const float v  = expf(pl[d]);
    const float th = expf(pl[D_DIM + d]);
    const float gamma = expf(pl[2 * D_DIM + d]);
    const float mg = expf(-v);
    const float2 lam = make_float2(mg * cosf(th), mg * sinf(th));

    // lambda^CHUNK via double trig (large angle; fast-math safe in double)
    const double ang = (double)th * (double)CHUNK;
    const float mgT = expf(-v * (float)CHUNK);
    const float2 lamT = make_float2(mgT * (float)cos(ang), mgT * (float)sin(ang));

    // exclusive prefix of chunk carries: E = sum_{j<c} lamT^{c-1-j} * carry_j
    const float2* c2 = (const float2*)carry;
    float2 E = make_float2(0.f, 0.f);
    for (int j = 0; j < c; j++) {
        const float2 cj = c2[(size_t)(b * NCHUNK + j) * D_DIM + d];
        float2 nE;
        nE.x = fmaf(lamT.x, E.x, fmaf(-lamT.y, E.y, cj.x));
        nE.y = fmaf(lamT.x, E.y, fmaf(lamT.y, E.x, cj.y));
        E = nE;
    }

    const float2* u2 = (const float2*)u;
    __half2* uh2 = (__half2*)uh;
    size_t off = (size_t)(b * L_DIM + c * CHUNK) * D_DIM + d;

    float2 f = lam;  // lambda^(t+1), iterated (no large-angle trig)
#pragma unroll 4
    for (int t = 0; t < CHUNK; t++) {
        float2 h = u2[off];
        float hr = (h.x + f.x * E.x - f.y * E.y) * gamma;
        float hi = (h.y + f.x * E.y + f.y * E.x) * gamma;
        uh2[off] = __floats2half2_rn(hr, hi);
        float2 nf;
        nf.x = f.x * lam.x - f.y * lam.y;
        nf.y = f.x * lam.y + f.y * lam.x;
        f = nf;
        off += D_DIM;
    }
}

// f32 -> f16 bulk convert, 8 elems/thread
__global__ void __launch_bounds__(256)
cvt_f2h(const float* __restrict__ src, __half* __restrict__ dst)
{
    const size_t i = (size_t)(blockIdx.x * blockDim.x + threadIdx.x) * 8;
    const float4 a = *(const float4*)(src + i);
    const float4 b = *(const float4*)(src + i + 4);
    __half2 h[4];
    h[0] = __floats2half2_rn(a.x, a.y);
    h[1] = __floats2half2_rn(a.z, a.w);
    h[2] = __floats2half2_rn(b.x, b.y);
    h[3] = __floats2half2_rn(b.z, b.w);
    *(uint4*)(dst + i) = *(const uint4*)h;
}

// Wo [N2, 2D] -> interleaved half: Wo2[n,2d]=Wo[n,d], Wo2[n,2d+1]=Wo[n,D+d]
__global__ void __launch_bounds__(256)
permute_wo_h(const float* __restrict__ Wo, __half* __restrict__ Wo2)
{
    const int idx = blockIdx.x * blockDim.x + threadIdx.x;  // N2*D
    const int d = idx % D_DIM;
    const int n = idx / D_DIM;
    const float a = Wo[(size_t)n * K2 + d];
    const float b = Wo[(size_t)n * K2 + D_DIM + d];
    ((__half2*)Wo2)[(size_t)n * D_DIM + d] = __floats2half2_rn(a, b);
}

// ---------------------------------------------------------------------------
extern "C" void kernel_launch(void* const* d_in, const int* in_sizes, int n_in,
                              void* d_out, int out_size)
{
    (void)in_sizes; (void)n_in; (void)out_size;
    const float* inputs = (const float*)d_in[0];
    const float* Wi     = (const float*)d_in[1];
    const float* bi     = (const float*)d_in[2];
    const float* Wo     = (const float*)d_in[3];
    const float* bo     = (const float*)d_in[4];
    const float* pl     = (const float*)d_in[5];
    float* out = (float*)d_out;

    float *u, *carry;
    __half *inh, *uh, *wih, *wo2h;
    cudaGetSymbolAddress((void**)&u, g_u);
    cudaGetSymbolAddress((void**)&carry, g_carry);
    cudaGetSymbolAddress((void**)&inh, g_inh);
    cudaGetSymbolAddress((void**)&uh, g_uh);
    cudaGetSymbolAddress((void**)&wih, g_wih);
    cudaGetSymbolAddress((void**)&wo2h, g_wo2h);

    cudaFuncSetAttribute(gemm_h<false>, cudaFuncAttributeMaxDynamicSharedMemorySize, GEMM_SMEM);
    cudaFuncSetAttribute(gemm_h<true>,  cudaFuncAttributeMaxDynamicSharedMemorySize, GEMM_SMEM);

    // prep: convert inputs + weights to half
    cvt_f2h<<<((size_t)M_DIM * K1 / 8) / 256, 256>>>(inputs, inh);
    cvt_f2h<<<((size_t)N1 * K1 / 8) / 256, 256>>>(Wi, wih);
    permute_wo_h<<<(N2 * D_DIM) / 256, 256>>>(Wo, wo2h);

    // GEMM1: u = inputs @ Wi^T + bi  (fp32 out)
    {
        dim3 grid(N1 / BNh, M_DIM / BMh);
        gemm_h<false><<<grid, 256, GEMM_SMEM>>>(inh, wih, bi, u, N1, K1);
    }

    // chunked complex scan; scan_fix emits half GEMM2 input
    scan_local<<<(B_DIM * NCHUNK * D_DIM) / 256, 256>>>(u, pl, carry);
    scan_fix<<<(B_DIM * NCHUNK * D_DIM) / 256, 256>>>(u, pl, carry, uh);

    // GEMM2: out = relu(h_interleaved @ Wo2^T + bo)
    {
        dim3 grid(N2 / BNh, M_DIM / BMh);
        gemm_h<true><<<grid, 256, GEMM_SMEM>>>(uh, wo2h, bo, out, N2, K2);
    }
}

// round 7
// speedup vs baseline: 1.6132x; 1.0753x over previous
#include <cuda_runtime.h>
#include <cuda_fp16.h>
#include <cstdint>
#include <cmath>

// ---------------------------------------------------------------------------
// Problem dims (fixed)
#define B_DIM 8
#define L_DIM 4096
#define D_DIM 512
#define M_DIM (B_DIM * L_DIM)   // 32768
#define N1 (2 * D_DIM)          // 1024
#define K1 (D_DIM)              // 512
#define N2 (D_DIM)              // 512
#define K2 (2 * D_DIM)          // 1024

#define CHUNK 256
#define NCHUNK (L_DIM / CHUNK)  // 16

// Scratch (device globals; allocation is banned)
__device__ __align__(1024) float  g_u[(size_t)M_DIM * N1];      // 128 MB fp32 (GEMM1 out / scan)
__device__ __align__(1024) __half g_inh[(size_t)M_DIM * K1];    // 32 MB  half inputs
__device__ __align__(1024) __half g_uh[(size_t)M_DIM * K2];     // 64 MB  half scan output (GEMM2 A)
__device__ __align__(1024) __half g_wih[(size_t)N1 * K1];       // 1 MB   half Wi
__device__ __align__(1024) __half g_wo2h[(size_t)N2 * K2];      // 1 MB   half permuted Wo
__device__ __align__(1024) float  g_carry[(size_t)B_DIM * NCHUNK * D_DIM * 2];

// ---------------------------------------------------------------------------
// fp16 TN GEMM: C[M,N] = A[M,K] * W[N,K]^T + bias (optional ReLU), fp32 accum.
// Block 128x128, BK=32 halves. 128 threads = 4 warps in 2x2, warp tile 64x64.
// ldmatrix.x4 fragment loads, 3-stage cp.async pipeline, padded smem (SSTH=40).
// ---------------------------------------------------------------------------
#define BMh 128
#define BNh 128
#define BKh 32
#define SSTH 40                     // halves per smem row (32 + 8 pad)
#define STAGE_HALVES (BMh * SSTH)   // per matrix per stage = 5120 halves
#define GEMM_SMEM (2 * 3 * STAGE_HALVES * 2)  // A+B, 3 stages, bytes = 61440

__device__ __forceinline__ void mma_f16(float* c, const uint32_t* a, const uint32_t* b) {
    asm volatile(
        "mma.sync.aligned.m16n8k16.row.col.f32.f16.f16.f32 "
        "{%0,%1,%2,%3},{%4,%5,%6,%7},{%8,%9},{%0,%1,%2,%3};\n"
        : "+f"(c[0]), "+f"(c[1]), "+f"(c[2]), "+f"(c[3])
        : "r"(a[0]), "r"(a[1]), "r"(a[2]), "r"(a[3]), "r"(b[0]), "r"(b[1]));
}

__device__ __forceinline__ void ldsm_x4(uint32_t& r0, uint32_t& r1,
                                        uint32_t& r2, uint32_t& r3, uint32_t addr) {
    asm volatile("ldmatrix.sync.aligned.m8n8.x4.shared.b16 {%0,%1,%2,%3}, [%4];"
        : "=r"(r0), "=r"(r1), "=r"(r2), "=r"(r3) : "r"(addr));
}

// one stage of cp.async loads: A[128 x 32h] + B[128 x 32h], 128 threads
__device__ __forceinline__ void ld_stage(uint32_t sA, uint32_t sB,
                                         const __half* gA, const __half* gB,
                                         int K, int tid)
{
#pragma unroll
    for (int i = 0; i < 4; i++) {
        const int c = tid + 128 * i;          // 0..511 chunk of 8 halves
        const int row  = c >> 2;
        const int col8 = (c & 3) * 8;
        const uint32_t so = (uint32_t)(row * SSTH + col8) * 2u;
        asm volatile("cp.async.ca.shared.global [%0], [%1], 16;\n"
                     ::"r"(sA + so), "l"(gA + (size_t)row * K + col8));
        asm volatile("cp.async.ca.shared.global [%0], [%1], 16;\n"
                     ::"r"(sB + so), "l"(gB + (size_t)row * K + col8));
    }
    asm volatile("cp.async.commit_group;\n");
}

template <bool RELU>
__global__ void __launch_bounds__(128, 2)
gemm_h(const __half* __restrict__ A, const __half* __restrict__ W,
       const float* __restrict__ bias, float* __restrict__ C,
       int N, int K)
{
    extern __shared__ __align__(16) __half smem[];
    __half* As = smem;                       // [3][128*SSTH]
    __half* Bs = smem + 3 * STAGE_HALVES;    // [3][128*SSTH]

    const int tid  = threadIdx.x;
    const int warp = tid >> 5;
    const int lane = tid & 31;
    const int g    = lane >> 2;   // 0..7
    const int tig  = lane & 3;    // 0..3
    const int wm   = warp >> 1;   // 0..1 -> m offset wm*64
    const int wn   = warp & 1;    // 0..1 -> n offset wn*64

    const int bm0 = blockIdx.y * BMh;
    const int bn0 = blockIdx.x * BNh;

    const __half* gA = A + (size_t)bm0 * K;
    const __half* gB = W + (size_t)bn0 * K;

    const uint32_t sA0 = (uint32_t)__cvta_generic_to_shared(As);
    const uint32_t sB0 = (uint32_t)__cvta_generic_to_shared(Bs);
    const uint32_t bufB = (uint32_t)STAGE_HALVES * 2u;  // bytes per stage

    // ldmatrix per-lane row/col (in halves)
    const int a_r  = (lane & 15);          // row within 16-row tile
    const int a_c8 = (lane >> 4) << 3;     // 0 or 8 (k halves)
    const int b_r  = ((lane >> 4) << 3) + (lane & 7);  // row within 16-row n tile
    const int b_c8 = ((lane >> 3) & 1) << 3;           // 0 or 8 (k halves)

    float acc[4][8][4];
#pragma unroll
    for (int mt = 0; mt < 4; mt++)
#pragma unroll
        for (int nt = 0; nt < 8; nt++)
#pragma unroll
            for (int i = 0; i < 4; i++) acc[mt][nt][i] = 0.f;

    const int KT = K / BKh;

    // prologue: stages 0 and 1
    ld_stage(sA0, sB0, gA, gB, K, tid);
    ld_stage(sA0 + bufB, sB0 + bufB, gA + BKh, gB + BKh, K, tid);

    for (int kt = 0; kt < KT; kt++) {
        if (kt + 1 < KT) asm volatile("cp.async.wait_group 1;\n");
        else             asm volatile("cp.async.wait_group 0;\n");
        __syncthreads();

        // prefetch tile kt+2 into buf (kt+2)%3
        if (kt + 2 < KT) {
            const uint32_t bo = (uint32_t)((kt + 2) % 3) * bufB;
            ld_stage(sA0 + bo, sB0 + bo, gA + (size_t)(kt + 2) * BKh,
                     gB + (size_t)(kt + 2) * BKh, K, tid);
        }

        const uint32_t sa = sA0 + (uint32_t)(kt % 3) * bufB;
        const uint32_t sb = sB0 + (uint32_t)(kt % 3) * bufB;

#pragma unroll
        for (int ks = 0; ks < 2; ks++) {
            const int k0 = ks * 16;
            uint32_t af[4][4], bf[8][2];
            // A fragments: 4 x ldmatrix.x4 (16x16 tiles)
#pragma unroll
            for (int mt = 0; mt < 4; mt++) {
                const int r = wm * 64 + mt * 16 + a_r;
                ldsm_x4(af[mt][0], af[mt][1], af[mt][2], af[mt][3],
                        sa + (uint32_t)(r * SSTH + a_c8 + k0) * 2u);
            }
            // B fragments: 4 x ldmatrix.x4, each covering two n-subtiles
#pragma unroll
            for (int ntp = 0; ntp < 4; ntp++) {
                const int r = wn * 64 + ntp * 16 + b_r;
                ldsm_x4(bf[2 * ntp][0], bf[2 * ntp][1],
                        bf[2 * ntp + 1][0], bf[2 * ntp + 1][1],
                        sb + (uint32_t)(r * SSTH + b_c8 + k0) * 2u);
            }
#pragma unroll
            for (int mt = 0; mt < 4; mt++)
#pragma unroll
                for (int nt = 0; nt < 8; nt++)
                    mma_f16(acc[mt][nt], af[mt], bf[nt]);
        }
        __syncthreads();
    }

    // epilogue: bias (+ ReLU), float2 stores
#pragma unroll
    for (int mt = 0; mt < 4; mt++) {
#pragma unroll
        for (int nt = 0; nt < 8; nt++) {
            const int row = bm0 + wm * 64 + mt * 16 + g;
            const int col = bn0 + wn * 64 + nt * 8 + tig * 2;
            const float b0 = bias[col];
            const float b1 = bias[col + 1];
            float2 v0, v1;
            v0.x = acc[mt][nt][0] + b0; v0.y = acc[mt][nt][1] + b1;
            v1.x = acc[mt][nt][2] + b0; v1.y = acc[mt][nt][3] + b1;
            if (RELU) {
                v0.x = fmaxf(v0.x, 0.f); v0.y = fmaxf(v0.y, 0.f);
                v1.x = fmaxf(v1.x, 0.f); v1.y = fmaxf(v1.y, 0.f);
            }
            *(float2*)&C[(size_t)row * N + col] = v0;
            *(float2*)&C[(size_t)(row + 8) * N + col] = v1;
        }
    }
}

// ---------------------------------------------------------------------------
// Scan kernels: h_t = lambda_d * h_{t-1} + x_t (complex), chunked 2-pass.
// u layout: [B, L, D] of float2 (re, im) interleaved.
// ---------------------------------------------------------------------------
__global__ void __launch_bounds__(256)
scan_local(float* __restrict__ u, const float* __restrict__ pl,
           float* __restrict__ carry)
{
    const int idx = blockIdx.x * blockDim.x + threadIdx.x;  // B*NCHUNK*D
    const int d = idx % D_DIM;
    const int c = (idx / D_DIM) % NCHUNK;
    const int b = idx / (D_DIM * NCHUNK);

    const float v  = expf(pl[d]);
    const float th = expf(pl[D_DIM + d]);
    const float mg = expf(-v);
    const float2 lam = make_float2(mg * cosf(th), mg * sinf(th));

    float2* u2 = (float2*)u;
    size_t off = (size_t)(b * L_DIM + c * CHUNK) * D_DIM + d;

    float2 h = make_float2(0.f, 0.f);
#pragma unroll 4
    for (int t = 0; t < CHUNK; t++) {
        float2 x = u2[off];
        float2 nh;
        nh.x = fmaf(lam.x, h.x, fmaf(-lam.y, h.y, x.x));
        nh.y = fmaf(lam.x, h.y, fmaf(lam.y, h.x, x.y));
        h = nh;
        u2[off] = h;
        off += D_DIM;
    }
    ((float2*)carry)[(size_t)(b * NCHUNK + c) * D_DIM + d] = h;
}

// Fused combine + fixup + gamma; writes half output for GEMM2 directly.
__global__ void __launch_bounds__(256)
scan_fix(const float* __restrict__ u, const float* __restrict__ pl,
         const float* __restrict__ carry, __half* __restrict__ uh)
{
    const int idx = blockIdx.x * blockDim.x + threadIdx.x;  // B*NCHUNK*D
    const int d = idx % D_DIM;
    const int c = (idx / D_DIM) % NCHUNK;
    const int b = idx / (D_DIM * NCHUNK);

    const float v  = expf(pl[d]);
    const float th = expf(pl[D_DIM + d]);
    const float gamma = expf(pl[2 * D_DIM + d]);
    const float mg = expf(-v);
    const float2 lam = make_float2(mg * cosf(th), mg * sinf(th));

    // lambda^CHUNK via double trig (large angle; fast-math safe in double)
    const double ang = (double)th * (double)CHUNK;
    const float mgT = expf(-v * (float)CHUNK);
    const float2 lamT = make_float2(mgT * (float)cos(ang), mgT * (float)sin(ang));

    // exclusive prefix of chunk carries: E = sum_{j<c} lamT^{c-1-j} * carry_j
    const float2* c2 = (const float2*)carry;
    float2 E = make_float2(0.f, 0.f);
    for (int j = 0; j < c; j++) {
        const float2 cj = c2[(size_t)(b * NCHUNK + j) * D_DIM + d];
        float2 nE;
        nE.x = fmaf(lamT.x, E.x, fmaf(-lamT.y, E.y, cj.x));
        nE.y = fmaf(lamT.x, E.y, fmaf(lamT.y, E.x, cj.y));
        E = nE;
    }

    const float2* u2 = (const float2*)u;
    __half2* uh2 = (__half2*)uh;
    size_t off = (size_t)(b * L_DIM + c * CHUNK) * D_DIM + d;

    float2 f = lam;  // lambda^(t+1), iterated (no large-angle trig)
#pragma unroll 4
    for (int t = 0; t < CHUNK; t++) {
        float2 h = u2[off];
        float hr = (h.x + f.x * E.x - f.y * E.y) * gamma;
        float hi = (h.y + f.x * E.y + f.y * E.x) * gamma;
        uh2[off] = __floats2half2_rn(hr, hi);
        float2 nf;
        nf.x = f.x * lam.x - f.y * lam.y;
        nf.y = f.x * lam.y + f.y * lam.x;
        f = nf;
        off += D_DIM;
    }
}

// f32 -> f16 bulk convert, 8 elems/thread
__global__ void __launch_bounds__(256)
cvt_f2h(const float* __restrict__ src, __half* __restrict__ dst)
{
    const size_t i = (size_t)(blockIdx.x * blockDim.x + threadIdx.x) * 8;
    const float4 a = *(const float4*)(src + i);
    const float4 b = *(const float4*)(src + i + 4);
    __half2 h[4];
    h[0] = __floats2half2_rn(a.x, a.y);
    h[1] = __floats2half2_rn(a.z, a.w);
    h[2] = __floats2half2_rn(b.x, b.y);
    h[3] = __floats2half2_rn(b.z, b.w);
    *(uint4*)(dst + i) = *(const uint4*)h;
}

// Wo [N2, 2D] -> interleaved half: Wo2[n,2d]=Wo[n,d], Wo2[n,2d+1]=Wo[n,D+d]
__global__ void __launch_bounds__(256)
permute_wo_h(const float* __restrict__ Wo, __half* __restrict__ Wo2)
{
    const int idx = blockIdx.x * blockDim.x + threadIdx.x;  // N2*D
    const int d = idx % D_DIM;
    const int n = idx / D_DIM;
    const float a = Wo[(size_t)n * K2 + d];
    const float b = Wo[(size_t)n * K2 + D_DIM + d];
    ((__half2*)Wo2)[(size_t)n * D_DIM + d] = __floats2half2_rn(a, b);
}

// ---------------------------------------------------------------------------
extern "C" void kernel_launch(void* const* d_in, const int* in_sizes, int n_in,
                              void* d_out, int out_size)
{
    (void)in_sizes; (void)n_in; (void)out_size;
    const float* inputs = (const float*)d_in[0];
    const float* Wi     = (const float*)d_in[1];
    const float* bi     = (const float*)d_in[2];
    const float* Wo     = (const float*)d_in[3];
    const float* bo     = (const float*)d_in[4];
    const float* pl     = (const float*)d_in[5];
    float* out = (float*)d_out;

    float *u, *carry;
    __half *inh, *uh, *wih, *wo2h;
    cudaGetSymbolAddress((void**)&u, g_u);
    cudaGetSymbolAddress((void**)&carry, g_carry);
    cudaGetSymbolAddress((void**)&inh, g_inh);
    cudaGetSymbolAddress((void**)&uh, g_uh);
    cudaGetSymbolAddress((void**)&wih, g_wih);
    cudaGetSymbolAddress((void**)&wo2h, g_wo2h);

    cudaFuncSetAttribute(gemm_h<false>, cudaFuncAttributeMaxDynamicSharedMemorySize, GEMM_SMEM);
    cudaFuncSetAttribute(gemm_h<true>,  cudaFuncAttributeMaxDynamicSharedMemorySize, GEMM_SMEM);

    // prep: convert inputs + weights to half
    cvt_f2h<<<((size_t)M_DIM * K1 / 8) / 256, 256>>>(inputs, inh);
    cvt_f2h<<<((size_t)N1 * K1 / 8) / 256, 256>>>(Wi, wih);
    permute_wo_h<<<(N2 * D_DIM) / 256, 256>>>(Wo, wo2h);

    // GEMM1: u = inputs @ Wi^T + bi  (fp32 out)
    {
        dim3 grid(N1 / BNh, M_DIM / BMh);
        gemm_h<false><<<grid, 128, GEMM_SMEM>>>(inh, wih, bi, u, N1, K1);
    }

    // chunked complex scan; scan_fix emits half GEMM2 input
    scan_local<<<(B_DIM * NCHUNK * D_DIM) / 256, 256>>>(u, pl, carry);
    scan_fix<<<(B_DIM * NCHUNK * D_DIM) / 256, 256>>>(u, pl, carry, uh);

    // GEMM2: out = relu(h_interleaved @ Wo2^T + bo)
    {
        dim3 grid(N2 / BNh, M_DIM / BMh);
        gemm_h<true><<<grid, 128, GEMM_SMEM>>>(uh, wo2h, bo, out, N2, K2);
    }
}